// round 5
// baseline (speedup 1.0000x reference)
#include <cuda_runtime.h>
#include <math.h>
#include <stdint.h>

// Problem constants
#define B_  256
#define T_  200
#define E_  584
#define H_  8
#define HS_ 73
#define BH_ (B_*H_)      // 2048
#define M_  (B_*T_)      // 51200

// Scratch (allocation-free rule: __device__ globals)
__device__ float g_q[BH_*T_*HS_];
__device__ float g_k[BH_*T_*HS_];
__device__ float g_v[BH_*T_*HS_];
__device__ float g_att[M_*E_];

__device__ __forceinline__ uint32_t f2tf32(float f) {
    uint32_t r;
    asm("cvt.rna.tf32.f32 %0, %1;" : "=r"(r) : "f"(f));
    return r;
}

__device__ __forceinline__ void mma_tf32(float c[4],
                                         uint32_t a0, uint32_t a1, uint32_t a2, uint32_t a3,
                                         uint32_t b0, uint32_t b1) {
    asm volatile(
        "mma.sync.aligned.m16n8k8.row.col.f32.tf32.tf32.f32 "
        "{%0,%1,%2,%3}, {%4,%5,%6,%7}, {%8,%9}, {%0,%1,%2,%3};"
        : "+f"(c[0]), "+f"(c[1]), "+f"(c[2]), "+f"(c[3])
        : "r"(a0), "r"(a1), "r"(a2), "r"(a3), "r"(b0), "r"(b1));
}

// ---------------------------------------------------------------------------
// TF32 tensor-core GEMM v2:  C[m,n] = sum_k A[m,k] * B[n,k]
// CTA tile 256x128, BK=16, 256 threads (8 warps as 4m x 2n), warp tile 64x64.
// smem: row-major, pitch ROWP=20 words (20 mod 32 => conflict-free frag reads).
// MODE 0: qkv projection  (A = x;     scatter to g_q/g_k/g_v)
// MODE 1: out projection  (A = g_att; +bias -> out)
// ---------------------------------------------------------------------------
#define ROWP 20
#define NSTG 37          // ceil(584/16)
#define A_WORDS (256*ROWP)
#define B_WORDS (128*ROWP)

template<int MODE>
__global__ __launch_bounds__(256)
void gemm_tf32(const float* __restrict__ Aarg,
               const float* __restrict__ B0,
               const float* __restrict__ B1,
               const float* __restrict__ B2,
               const float* __restrict__ bias,
               float* __restrict__ out)
{
    extern __shared__ uint32_t sh[];
    uint32_t* Asm = sh;                    // [2][256*ROWP]
    uint32_t* Bsm = sh + 2 * A_WORDS;      // [2][128*ROWP]

    const float* A = (MODE == 0) ? Aarg : (const float*)g_att;

    const int tid  = threadIdx.x;
    const int lane = tid & 31;
    const int w    = tid >> 5;
    const int g    = lane >> 2;
    const int c    = lane & 3;
    const int wm   = w & 3;          // 4 m-warps, 64 rows each
    const int wn   = w >> 2;         // 2 n-warps, 64 cols each

    const int m0 = blockIdx.y * 256;
    const int n0 = blockIdx.x * 128;

    float acc[4][8][4];
#pragma unroll
    for (int mi = 0; mi < 4; mi++)
#pragma unroll
        for (int ni = 0; ni < 8; ni++)
#pragma unroll
            for (int r = 0; r < 4; r++) acc[mi][ni][r] = 0.f;

    // staging: thread handles rows ar+64*i (A: i=0..3, B: i=0..1), k-chunk kc
    const int ar = tid >> 2;
    const int kc = tid & 3;

    const float* aptr[4];
#pragma unroll
    for (int i = 0; i < 4; i++)
        aptr[i] = A + (size_t)(m0 + ar + 64*i) * E_ + kc * 4;

    const float* bptr[2];
    bool bval[2];
#pragma unroll
    for (int i = 0; i < 2; i++) {
        int gn = n0 + ar + 64*i;
        if (MODE == 0) {
            bval[i] = gn < 3 * E_;
            int s = gn / E_; if (s > 2) s = 2;
            int l = bval[i] ? gn - s * E_ : 0;
            const float* W = (s == 0) ? B0 : ((s == 1) ? B1 : B2);
            bptr[i] = W + (size_t)l * E_ + kc * 4;
        } else {
            bval[i] = gn < E_;
            bptr[i] = B0 + (size_t)(bval[i] ? gn : 0) * E_ + kc * 4;
        }
    }

    const float4 z4 = make_float4(0.f, 0.f, 0.f, 0.f);

    // ---- prologue: stage 0 into buffer 0 (k0=0 always in-bounds) ----------
    {
        uint32_t* as = Asm;
        uint32_t* bs = Bsm;
#pragma unroll
        for (int i = 0; i < 4; i++) {
            float4 v = *(const float4*)aptr[i];
            uint32_t* p = as + (ar + 64*i) * ROWP + kc * 4;
            p[0] = f2tf32(v.x); p[1] = f2tf32(v.y); p[2] = f2tf32(v.z); p[3] = f2tf32(v.w);
        }
#pragma unroll
        for (int i = 0; i < 2; i++) {
            float4 v = bval[i] ? *(const float4*)bptr[i] : z4;
            uint32_t* p = bs + (ar + 64*i) * ROWP + kc * 4;
            p[0] = f2tf32(v.x); p[1] = f2tf32(v.y); p[2] = f2tf32(v.z); p[3] = f2tf32(v.w);
        }
    }
    __syncthreads();

#pragma unroll 1
    for (int s = 0; s < NSTG; s++) {
        const int buf = s & 1;
        const uint32_t* as = Asm + buf * A_WORDS;
        const uint32_t* bs = Bsm + buf * B_WORDS;

        // issue global loads for next stage
        float4 na[4], nb[2];
        const bool more = (s + 1 < NSTG);
        if (more) {
            const int k0 = (s + 1) * 16;
            const bool kok = (k0 + kc * 4) < E_;
#pragma unroll
            for (int i = 0; i < 4; i++) na[i] = kok ? *(const float4*)(aptr[i] + k0) : z4;
#pragma unroll
            for (int i = 0; i < 2; i++) nb[i] = (kok && bval[i]) ? *(const float4*)(bptr[i] + k0) : z4;
        }

        // ---- compute half ks=0 ------------------------------------------
        {
            uint32_t af[4][4], bf[8][2];
#pragma unroll
            for (int mi = 0; mi < 4; mi++) {
                const int row = wm * 64 + mi * 16 + g;
                af[mi][0] = as[row       * ROWP + c];
                af[mi][1] = as[(row + 8) * ROWP + c];
                af[mi][2] = as[row       * ROWP + c + 4];
                af[mi][3] = as[(row + 8) * ROWP + c + 4];
            }
#pragma unroll
            for (int ni = 0; ni < 8; ni++) {
                const int row = wn * 64 + ni * 8 + g;
                bf[ni][0] = bs[row * ROWP + c];
                bf[ni][1] = bs[row * ROWP + c + 4];
            }
#pragma unroll
            for (int mi = 0; mi < 4; mi++)
#pragma unroll
                for (int ni = 0; ni < 8; ni++)
                    mma_tf32(acc[mi][ni], af[mi][0], af[mi][1], af[mi][2], af[mi][3],
                             bf[ni][0], bf[ni][1]);
        }

        // store next stage (frees staging regs before half 1)
        if (more) {
            uint32_t* asn = Asm + (buf ^ 1) * A_WORDS;
            uint32_t* bsn = Bsm + (buf ^ 1) * B_WORDS;
#pragma unroll
            for (int i = 0; i < 4; i++) {
                uint32_t* p = asn + (ar + 64*i) * ROWP + kc * 4;
                p[0] = f2tf32(na[i].x); p[1] = f2tf32(na[i].y);
                p[2] = f2tf32(na[i].z); p[3] = f2tf32(na[i].w);
            }
#pragma unroll
            for (int i = 0; i < 2; i++) {
                uint32_t* p = bsn + (ar + 64*i) * ROWP + kc * 4;
                p[0] = f2tf32(nb[i].x); p[1] = f2tf32(nb[i].y);
                p[2] = f2tf32(nb[i].z); p[3] = f2tf32(nb[i].w);
            }
        }

        // ---- compute half ks=8 ------------------------------------------
        {
            uint32_t af[4][4], bf[8][2];
#pragma unroll
            for (int mi = 0; mi < 4; mi++) {
                const int row = wm * 64 + mi * 16 + g;
                af[mi][0] = as[row       * ROWP + 8 + c];
                af[mi][1] = as[(row + 8) * ROWP + 8 + c];
                af[mi][2] = as[row       * ROWP + 8 + c + 4];
                af[mi][3] = as[(row + 8) * ROWP + 8 + c + 4];
            }
#pragma unroll
            for (int ni = 0; ni < 8; ni++) {
                const int row = wn * 64 + ni * 8 + g;
                bf[ni][0] = bs[row * ROWP + 8 + c];
                bf[ni][1] = bs[row * ROWP + 8 + c + 4];
            }
#pragma unroll
            for (int mi = 0; mi < 4; mi++)
#pragma unroll
                for (int ni = 0; ni < 8; ni++)
                    mma_tf32(acc[mi][ni], af[mi][0], af[mi][1], af[mi][2], af[mi][3],
                             bf[ni][0], bf[ni][1]);
        }

        __syncthreads();
    }

    // ---- epilogue -----------------------------------------------------------
#pragma unroll
    for (int mi = 0; mi < 4; mi++) {
#pragma unroll
        for (int ni = 0; ni < 8; ni++) {
#pragma unroll
            for (int r = 0; r < 4; r++) {
                const int m = m0 + wm * 64 + mi * 16 + g + ((r >= 2) ? 8 : 0);
                const int n = n0 + wn * 64 + ni * 8 + 2 * c + (r & 1);
                const float v = acc[mi][ni][r];
                if (MODE == 0) {
                    if (n < 3 * E_) {
                        const int sidx = n / E_;
                        const int l    = n - sidx * E_;
                        const int hh   = l / HS_;
                        const int f    = l - hh * HS_;
                        const int bb   = m / T_;
                        const int t    = m - bb * T_;
                        float* dst = (sidx == 0) ? g_q : ((sidx == 1) ? g_k : g_v);
                        dst[((size_t)(bb * H_ + hh) * T_ + t) * HS_ + f] = v;
                    }
                } else {
                    if (n < E_)
                        out[(size_t)m * E_ + n] = v + bias[n];
                }
            }
        }
    }
}

// ---------------------------------------------------------------------------
// Tensor-core attention (unchanged from R4, passing @ rel_err 4.7e-4)
// ---------------------------------------------------------------------------
#define TP2 208
#define FP2 80
#define QP  84
#define KQ2 84
#define VP  88
#define PP  212

__global__ __launch_bounds__(256, 1)
void attn_mma()
{
    extern __shared__ uint32_t smu[];
    uint32_t* Ks = smu;
    uint32_t* Vs = Ks + TP2*KQ2;
    uint32_t* Qs = Vs + TP2*VP;
    uint32_t* Pt = Qs + 64*QP;
    float* pmax  = (float*)(Pt + 64*PP);
    float* psum  = pmax + 128;

    const int bh   = blockIdx.x;
    const int tid  = threadIdx.x;
    const int lane = tid & 31;
    const int w    = tid >> 5;
    const int g    = lane >> 2;
    const int c    = lane & 3;
    const int wm   = w & 3;
    const int wn   = w >> 2;
    const int b    = bh / H_;
    const int h    = bh - b * H_;

    const float* qg = g_q + (size_t)bh * T_ * HS_;
    const float* kg = g_k + (size_t)bh * T_ * HS_;
    const float* vg = g_v + (size_t)bh * T_ * HS_;

    for (int i = tid; i < TP2*KQ2; i += 256) {
        const int s = i / KQ2, f = i - s * KQ2;
        Ks[i] = (s < T_ && f < HS_) ? f2tf32(kg[s*HS_ + f]) : 0u;
    }
    for (int i = tid; i < TP2*VP; i += 256) {
        const int s = i / VP, f = i - s * VP;
        Vs[i] = (s < T_ && f < HS_) ? f2tf32(vg[s*HS_ + f]) : 0u;
    }

    const float scale = rsqrtf((float)E_);
    const int mr = wm * 16;

    for (int t0 = 0; t0 < T_; t0 += 64) {
        __syncthreads();
        for (int i = tid; i < 64*QP; i += 256) {
            const int r = i / QP, f = i - r * QP;
            const int tg = t0 + r;
            Qs[i] = (tg < T_ && f < HS_) ? f2tf32(qg[tg*HS_ + f]) : 0u;
        }
        __syncthreads();

        const int nb  = wn * 104;
        const int thi = t0 + mr + 15;
        float acc[13][4];
#pragma unroll
        for (int ni = 0; ni < 13; ni++)
#pragma unroll
            for (int r = 0; r < 4; r++) acc[ni][r] = 0.f;

        for (int ks = 0; ks < FP2; ks += 8) {
            const uint32_t a0 = Qs[(mr+g)  *QP + ks+c];
            const uint32_t a1 = Qs[(mr+g+8)*QP + ks+c];
            const uint32_t a2 = Qs[(mr+g)  *QP + ks+c+4];
            const uint32_t a3 = Qs[(mr+g+8)*QP + ks+c+4];
#pragma unroll
            for (int ni = 0; ni < 13; ni++) {
                if (nb + ni*8 <= thi) {
                    const uint32_t b0 = Ks[(nb+ni*8+g)*KQ2 + ks+c];
                    const uint32_t b1 = Ks[(nb+ni*8+g)*KQ2 + ks+c+4];
                    mma_tf32(acc[ni], a0, a1, a2, a3, b0, b1);
                }
            }
        }

        const int t_lo = t0 + mr + g;
        const int t_hi = t_lo + 8;

        float mlo = -1e30f, mhi = -1e30f;
#pragma unroll
        for (int ni = 0; ni < 13; ni++) {
            const int s0 = nb + ni*8 + 2*c;
            const int s1 = s0 + 1;
            const bool ok0l = (s0 <= t_lo) && (s0 < T_) && (t_lo < T_);
            const bool ok1l = (s1 <= t_lo) && (s1 < T_) && (t_lo < T_);
            const bool ok0h = (s0 <= t_hi) && (s0 < T_) && (t_hi < T_);
            const bool ok1h = (s1 <= t_hi) && (s1 < T_) && (t_hi < T_);
            if (ok0l) mlo = fmaxf(mlo, acc[ni][0]*scale);
            if (ok1l) mlo = fmaxf(mlo, acc[ni][1]*scale);
            if (ok0h) mhi = fmaxf(mhi, acc[ni][2]*scale);
            if (ok1h) mhi = fmaxf(mhi, acc[ni][3]*scale);
        }
#pragma unroll
        for (int off = 1; off <= 2; off <<= 1) {
            mlo = fmaxf(mlo, __shfl_xor_sync(0xffffffffu, mlo, off));
            mhi = fmaxf(mhi, __shfl_xor_sync(0xffffffffu, mhi, off));
        }
        if (c == 0) {
            pmax[(mr+g)  *2 + wn] = mlo;
            pmax[(mr+g+8)*2 + wn] = mhi;
        }
        __syncthreads();
        const float gmlo = fmaxf(pmax[(mr+g)*2],   pmax[(mr+g)*2+1]);
        const float gmhi = fmaxf(pmax[(mr+g+8)*2], pmax[(mr+g+8)*2+1]);

        float slo = 0.f, shi = 0.f;
#pragma unroll
        for (int ni = 0; ni < 13; ni++) {
            const int s0 = nb + ni*8 + 2*c;
            const int s1 = s0 + 1;
            const bool ok0l = (s0 <= t_lo) && (s0 < T_) && (t_lo < T_);
            const bool ok1l = (s1 <= t_lo) && (s1 < T_) && (t_lo < T_);
            const bool ok0h = (s0 <= t_hi) && (s0 < T_) && (t_hi < T_);
            const bool ok1h = (s1 <= t_hi) && (s1 < T_) && (t_hi < T_);
            float e0 = ok0l ? __expf(acc[ni][0]*scale - gmlo) : 0.f;
            float e1 = ok1l ? __expf(acc[ni][1]*scale - gmlo) : 0.f;
            float e2 = ok0h ? __expf(acc[ni][2]*scale - gmhi) : 0.f;
            float e3 = ok1h ? __expf(acc[ni][3]*scale - gmhi) : 0.f;
            acc[ni][0] = e0; acc[ni][1] = e1; acc[ni][2] = e2; acc[ni][3] = e3;
            slo += e0 + e1;  shi += e2 + e3;
        }
#pragma unroll
        for (int off = 1; off <= 2; off <<= 1) {
            slo += __shfl_xor_sync(0xffffffffu, slo, off);
            shi += __shfl_xor_sync(0xffffffffu, shi, off);
        }
        if (c == 0) {
            psum[(mr+g)  *2 + wn] = slo;
            psum[(mr+g+8)*2 + wn] = shi;
        }
        __syncthreads();
        const float tlo  = psum[(mr+g)*2]   + psum[(mr+g)*2+1];
        const float thi2 = psum[(mr+g+8)*2] + psum[(mr+g+8)*2+1];
        const float rlo = (tlo  > 0.f) ? (1.f / tlo)  : 0.f;
        const float rhi = (thi2 > 0.f) ? (1.f / thi2) : 0.f;

#pragma unroll
        for (int ni = 0; ni < 13; ni++) {
            const int col = nb + ni*8 + 2*c;
            uint2 ulo = make_uint2(f2tf32(acc[ni][0]*rlo), f2tf32(acc[ni][1]*rlo));
            uint2 uhi = make_uint2(f2tf32(acc[ni][2]*rhi), f2tf32(acc[ni][3]*rhi));
            *(uint2*)&Pt[(mr+g)  *PP + col] = ulo;
            *(uint2*)&Pt[(mr+g+8)*PP + col] = uhi;
        }
        __syncthreads();

        const int nb2 = wn * 40;
        float o[5][4];
#pragma unroll
        for (int ni = 0; ni < 5; ni++)
#pragma unroll
            for (int r = 0; r < 4; r++) o[ni][r] = 0.f;

        const int kcap   = (thi < T_-1) ? thi : (T_-1);
        const int ks_end = kcap >> 3;
        for (int ksb = 0; ksb <= ks_end; ksb++) {
            const int ks = ksb * 8;
            const uint32_t a0 = Pt[(mr+g)  *PP + ks+c];
            const uint32_t a1 = Pt[(mr+g+8)*PP + ks+c];
            const uint32_t a2 = Pt[(mr+g)  *PP + ks+c+4];
            const uint32_t a3 = Pt[(mr+g+8)*PP + ks+c+4];
#pragma unroll
            for (int ni = 0; ni < 5; ni++) {
                const uint32_t b0 = Vs[(ks+c)  *VP + nb2+ni*8+g];
                const uint32_t b1 = Vs[(ks+c+4)*VP + nb2+ni*8+g];
                mma_tf32(o[ni], a0, a1, a2, a3, b0, b1);
            }
        }

#pragma unroll
        for (int ni = 0; ni < 5; ni++) {
#pragma unroll
            for (int r = 0; r < 4; r++) {
                const int t = t0 + mr + g + ((r >= 2) ? 8 : 0);
                const int f = nb2 + ni*8 + 2*c + (r & 1);
                if (t < T_ && f < HS_)
                    g_att[((size_t)(b*T_ + t))*E_ + h*HS_ + f] = o[ni][r];
            }
        }
    }
}

// ---------------------------------------------------------------------------
extern "C" void kernel_launch(void* const* d_in, const int* in_sizes, int n_in,
                              void* d_out, int out_size)
{
    const float* x  = (const float*)d_in[0];
    const float* Wq = (const float*)d_in[1];
    const float* Wk = (const float*)d_in[2];
    const float* Wv = (const float*)d_in[3];
    const float* Wo = (const float*)d_in[4];
    const float* bo = (const float*)d_in[5];
    float* out = (float*)d_out;

    const int gemm_smem = (A_WORDS + B_WORDS) * 2 * (int)sizeof(uint32_t);   // 61440
    cudaFuncSetAttribute(gemm_tf32<0>, cudaFuncAttributeMaxDynamicSharedMemorySize, gemm_smem);
    cudaFuncSetAttribute(gemm_tf32<1>, cudaFuncAttributeMaxDynamicSharedMemorySize, gemm_smem);

    const int att_smem = (TP2*KQ2 + TP2*VP + 64*QP + 64*PP + 256) * (int)sizeof(float);
    cudaFuncSetAttribute(attn_mma, cudaFuncAttributeMaxDynamicSharedMemorySize, att_smem);

    // QKV projection: M=51200 -> 200 tiles of 256, N=1752 -> 14 tiles of 128
    gemm_tf32<0><<<dim3(14, 200), 256, gemm_smem>>>(x, Wq, Wk, Wv, nullptr, nullptr);

    // attention (tensor-core)
    attn_mma<<<BH_, 256, att_smem>>>();

    // output projection: N=584 -> 5 tiles
    gemm_tf32<1><<<dim3(5, 200), 256, gemm_smem>>>(nullptr, Wo, nullptr, nullptr, bo, out);
}

// round 6
// speedup vs baseline: 1.0540x; 1.0540x over previous
#include <cuda_runtime.h>
#include <math.h>
#include <stdint.h>

// Problem constants
#define B_  256
#define T_  200
#define E_  584
#define H_  8
#define HS_ 73
#define BH_ (B_*H_)      // 2048
#define M_  (B_*T_)      // 51200

// Scratch (allocation-free rule: __device__ globals)
__device__ float g_q[BH_*T_*HS_];
__device__ float g_k[BH_*T_*HS_];
__device__ float g_v[BH_*T_*HS_];
__device__ float g_att[M_*E_];

__device__ __forceinline__ uint32_t f2tf32(float f) {
    uint32_t r;
    asm("cvt.rna.tf32.f32 %0, %1;" : "=r"(r) : "f"(f));
    return r;
}

__device__ __forceinline__ void mma_tf32(float c[4],
                                         uint32_t a0, uint32_t a1, uint32_t a2, uint32_t a3,
                                         uint32_t b0, uint32_t b1) {
    asm volatile(
        "mma.sync.aligned.m16n8k8.row.col.f32.tf32.tf32.f32 "
        "{%0,%1,%2,%3}, {%4,%5,%6,%7}, {%8,%9}, {%0,%1,%2,%3};"
        : "+f"(c[0]), "+f"(c[1]), "+f"(c[2]), "+f"(c[3])
        : "r"(a0), "r"(a1), "r"(a2), "r"(a3), "r"(b0), "r"(b1));
}

__device__ __forceinline__ uint32_t s2u(const void* p) {
    return (uint32_t)__cvta_generic_to_shared(p);
}
__device__ __forceinline__ void cp16(uint32_t d, const void* s, bool v) {
    asm volatile("cp.async.ca.shared.global [%0], [%1], 16, %2;"
                 :: "r"(d), "l"(s), "r"(v ? 16 : 0));
}
__device__ __forceinline__ void cp_commit() {
    asm volatile("cp.async.commit_group;");
}
__device__ __forceinline__ void cp_wait1() {
    asm volatile("cp.async.wait_group 1;");
}

// ---------------------------------------------------------------------------
// TF32 tensor-core GEMM v3 (cp.async 3-stage pipeline):
//   C[m,n] = sum_k A[m,k] * B[n,k]
// CTA tile 128x128, BK=16, 256 threads (8 warps as 4m x 2n), warp tile 32x64.
// smem: raw f32, row-major, pitch ROWP=20 (mod 32 => conflict-free frags).
// tf32 conversion on fragment load. 2 CTAs/SM.
// MODE 0: qkv projection  (A = x;     scatter to g_q/g_k/g_v)
// MODE 1: out projection  (A = g_att; +bias -> out)
// ---------------------------------------------------------------------------
#define ROWP   20
#define BK     16
#define STAGES 3
#define NSTG   37          // ceil(584/16)
#define TILE_WORDS (128*ROWP)

template<int MODE>
__global__ __launch_bounds__(256, 2)
void gemm_tf32(const float* __restrict__ Aarg,
               const float* __restrict__ B0,
               const float* __restrict__ B1,
               const float* __restrict__ B2,
               const float* __restrict__ bias,
               float* __restrict__ out)
{
    __shared__ float As[STAGES][TILE_WORDS];
    __shared__ float Bs[STAGES][TILE_WORDS];

    const float* A = (MODE == 0) ? Aarg : (const float*)g_att;

    const int tid  = threadIdx.x;
    const int lane = tid & 31;
    const int w    = tid >> 5;
    const int g    = lane >> 2;
    const int c    = lane & 3;
    const int wm   = w & 3;          // 4 m-warps, 32 rows each
    const int wn   = w >> 2;         // 2 n-warps, 64 cols each

    const int m0 = blockIdx.y * 128;
    const int n0 = blockIdx.x * 128;

    float acc[2][8][4];
#pragma unroll
    for (int mi = 0; mi < 2; mi++)
#pragma unroll
        for (int ni = 0; ni < 8; ni++)
#pragma unroll
            for (int r = 0; r < 4; r++) acc[mi][ni][r] = 0.f;

    // staging: thread owns tile row (tid>>1), two 16B chunks at kcp, kcp+1
    const int row = tid >> 1;
    const int kcp = (tid & 1) * 2;      // chunk base: floats kcp*4 .. kcp*4+7

    const float* aptr = A + (size_t)(m0 + row) * E_ + kcp * 4;

    const float* bptr;
    bool bval;
    {
        int gn = n0 + row;
        if (MODE == 0) {
            bval = gn < 3 * E_;
            int s = gn / E_; if (s > 2) s = 2;
            int l = bval ? gn - s * E_ : 0;
            const float* W = (s == 0) ? B0 : ((s == 1) ? B1 : B2);
            bptr = W + (size_t)l * E_ + kcp * 4;
        } else {
            bval = gn < E_;
            bptr = B0 + (size_t)(bval ? gn : 0) * E_ + kcp * 4;
        }
    }

    const uint32_t a_s0 = s2u(&As[0][row * ROWP + kcp * 4]);
    const uint32_t b_s0 = s2u(&Bs[0][row * ROWP + kcp * 4]);
    const uint32_t stage_bytes = TILE_WORDS * 4;

    // issue cp.async group for stage s
    auto issue = [&](int s) {
        if (s < NSTG) {
            const int k0 = s * BK;
            const int slot = s % STAGES;
            const bool v0 = (k0 + kcp * 4)     < E_;
            const bool v1 = (k0 + kcp * 4 + 4) < E_;
            const uint32_t ad = a_s0 + slot * stage_bytes;
            const uint32_t bd = b_s0 + slot * stage_bytes;
            cp16(ad,      aptr + k0,     v0);
            cp16(ad + 16, aptr + k0 + 4, v1);
            cp16(bd,      bptr + k0,     v0 && bval);
            cp16(bd + 16, bptr + k0 + 4, v1 && bval);
        }
        cp_commit();
    };

    // prologue: stages 0,1 in flight
    issue(0);
    issue(1);

#pragma unroll 1
    for (int s = 0; s < NSTG; s++) {
        cp_wait1();            // stage s landed (<=1 group still in flight)
        __syncthreads();       // visible to all warps; slot (s-1)%3 free

        issue(s + 2);          // refill into slot (s+2)%3 == (s-1)%3

        const float* as = As[s % STAGES];
        const float* bs = Bs[s % STAGES];

#pragma unroll
        for (int ks = 0; ks < BK; ks += 8) {
            uint32_t af[2][4], bf[8][2];
#pragma unroll
            for (int mi = 0; mi < 2; mi++) {
                const int r0 = wm * 32 + mi * 16 + g;
                af[mi][0] = f2tf32(as[r0       * ROWP + ks + c]);
                af[mi][1] = f2tf32(as[(r0 + 8) * ROWP + ks + c]);
                af[mi][2] = f2tf32(as[r0       * ROWP + ks + c + 4]);
                af[mi][3] = f2tf32(as[(r0 + 8) * ROWP + ks + c + 4]);
            }
#pragma unroll
            for (int ni = 0; ni < 8; ni++) {
                const int r0 = wn * 64 + ni * 8 + g;
                bf[ni][0] = f2tf32(bs[r0 * ROWP + ks + c]);
                bf[ni][1] = f2tf32(bs[r0 * ROWP + ks + c + 4]);
            }
#pragma unroll
            for (int mi = 0; mi < 2; mi++)
#pragma unroll
                for (int ni = 0; ni < 8; ni++)
                    mma_tf32(acc[mi][ni], af[mi][0], af[mi][1], af[mi][2], af[mi][3],
                             bf[ni][0], bf[ni][1]);
        }
    }

    // ---- epilogue -----------------------------------------------------------
#pragma unroll
    for (int mi = 0; mi < 2; mi++) {
#pragma unroll
        for (int ni = 0; ni < 8; ni++) {
#pragma unroll
            for (int r = 0; r < 4; r++) {
                const int m = m0 + wm * 32 + mi * 16 + g + ((r >= 2) ? 8 : 0);
                const int n = n0 + wn * 64 + ni * 8 + 2 * c + (r & 1);
                const float v = acc[mi][ni][r];
                if (MODE == 0) {
                    if (n < 3 * E_) {
                        const int sidx = n / E_;
                        const int l    = n - sidx * E_;
                        const int hh   = l / HS_;
                        const int f    = l - hh * HS_;
                        const int bb   = m / T_;
                        const int t    = m - bb * T_;
                        float* dst = (sidx == 0) ? g_q : ((sidx == 1) ? g_k : g_v);
                        dst[((size_t)(bb * H_ + hh) * T_ + t) * HS_ + f] = v;
                    }
                } else {
                    if (n < E_)
                        out[(size_t)m * E_ + n] = v + bias[n];
                }
            }
        }
    }
}

// ---------------------------------------------------------------------------
// Tensor-core attention (unchanged; passing @ rel_err 4.7e-4)
// ---------------------------------------------------------------------------
#define TP2 208
#define FP2 80
#define QP  84
#define KQ2 84
#define VP  88
#define PP  212

__global__ __launch_bounds__(256, 1)
void attn_mma()
{
    extern __shared__ uint32_t smu[];
    uint32_t* Ks = smu;
    uint32_t* Vs = Ks + TP2*KQ2;
    uint32_t* Qs = Vs + TP2*VP;
    uint32_t* Pt = Qs + 64*QP;
    float* pmax  = (float*)(Pt + 64*PP);
    float* psum  = pmax + 128;

    const int bh   = blockIdx.x;
    const int tid  = threadIdx.x;
    const int lane = tid & 31;
    const int w    = tid >> 5;
    const int g    = lane >> 2;
    const int c    = lane & 3;
    const int wm   = w & 3;
    const int wn   = w >> 2;
    const int b    = bh / H_;
    const int h    = bh - b * H_;

    const float* qg = g_q + (size_t)bh * T_ * HS_;
    const float* kg = g_k + (size_t)bh * T_ * HS_;
    const float* vg = g_v + (size_t)bh * T_ * HS_;

    for (int i = tid; i < TP2*KQ2; i += 256) {
        const int s = i / KQ2, f = i - s * KQ2;
        Ks[i] = (s < T_ && f < HS_) ? f2tf32(kg[s*HS_ + f]) : 0u;
    }
    for (int i = tid; i < TP2*VP; i += 256) {
        const int s = i / VP, f = i - s * VP;
        Vs[i] = (s < T_ && f < HS_) ? f2tf32(vg[s*HS_ + f]) : 0u;
    }

    const float scale = rsqrtf((float)E_);
    const int mr = wm * 16;

    for (int t0 = 0; t0 < T_; t0 += 64) {
        __syncthreads();
        for (int i = tid; i < 64*QP; i += 256) {
            const int r = i / QP, f = i - r * QP;
            const int tg = t0 + r;
            Qs[i] = (tg < T_ && f < HS_) ? f2tf32(qg[tg*HS_ + f]) : 0u;
        }
        __syncthreads();

        const int nb  = wn * 104;
        const int thi = t0 + mr + 15;
        float acc[13][4];
#pragma unroll
        for (int ni = 0; ni < 13; ni++)
#pragma unroll
            for (int r = 0; r < 4; r++) acc[ni][r] = 0.f;

        for (int ks = 0; ks < FP2; ks += 8) {
            const uint32_t a0 = Qs[(mr+g)  *QP + ks+c];
            const uint32_t a1 = Qs[(mr+g+8)*QP + ks+c];
            const uint32_t a2 = Qs[(mr+g)  *QP + ks+c+4];
            const uint32_t a3 = Qs[(mr+g+8)*QP + ks+c+4];
#pragma unroll
            for (int ni = 0; ni < 13; ni++) {
                if (nb + ni*8 <= thi) {
                    const uint32_t b0 = Ks[(nb+ni*8+g)*KQ2 + ks+c];
                    const uint32_t b1 = Ks[(nb+ni*8+g)*KQ2 + ks+c+4];
                    mma_tf32(acc[ni], a0, a1, a2, a3, b0, b1);
                }
            }
        }

        const int t_lo = t0 + mr + g;
        const int t_hi = t_lo + 8;

        float mlo = -1e30f, mhi = -1e30f;
#pragma unroll
        for (int ni = 0; ni < 13; ni++) {
            const int s0 = nb + ni*8 + 2*c;
            const int s1 = s0 + 1;
            const bool ok0l = (s0 <= t_lo) && (s0 < T_) && (t_lo < T_);
            const bool ok1l = (s1 <= t_lo) && (s1 < T_) && (t_lo < T_);
            const bool ok0h = (s0 <= t_hi) && (s0 < T_) && (t_hi < T_);
            const bool ok1h = (s1 <= t_hi) && (s1 < T_) && (t_hi < T_);
            if (ok0l) mlo = fmaxf(mlo, acc[ni][0]*scale);
            if (ok1l) mlo = fmaxf(mlo, acc[ni][1]*scale);
            if (ok0h) mhi = fmaxf(mhi, acc[ni][2]*scale);
            if (ok1h) mhi = fmaxf(mhi, acc[ni][3]*scale);
        }
#pragma unroll
        for (int off = 1; off <= 2; off <<= 1) {
            mlo = fmaxf(mlo, __shfl_xor_sync(0xffffffffu, mlo, off));
            mhi = fmaxf(mhi, __shfl_xor_sync(0xffffffffu, mhi, off));
        }
        if (c == 0) {
            pmax[(mr+g)  *2 + wn] = mlo;
            pmax[(mr+g+8)*2 + wn] = mhi;
        }
        __syncthreads();
        const float gmlo = fmaxf(pmax[(mr+g)*2],   pmax[(mr+g)*2+1]);
        const float gmhi = fmaxf(pmax[(mr+g+8)*2], pmax[(mr+g+8)*2+1]);

        float slo = 0.f, shi = 0.f;
#pragma unroll
        for (int ni = 0; ni < 13; ni++) {
            const int s0 = nb + ni*8 + 2*c;
            const int s1 = s0 + 1;
            const bool ok0l = (s0 <= t_lo) && (s0 < T_) && (t_lo < T_);
            const bool ok1l = (s1 <= t_lo) && (s1 < T_) && (t_lo < T_);
            const bool ok0h = (s0 <= t_hi) && (s0 < T_) && (t_hi < T_);
            const bool ok1h = (s1 <= t_hi) && (s1 < T_) && (t_hi < T_);
            float e0 = ok0l ? __expf(acc[ni][0]*scale - gmlo) : 0.f;
            float e1 = ok1l ? __expf(acc[ni][1]*scale - gmlo) : 0.f;
            float e2 = ok0h ? __expf(acc[ni][2]*scale - gmhi) : 0.f;
            float e3 = ok1h ? __expf(acc[ni][3]*scale - gmhi) : 0.f;
            acc[ni][0] = e0; acc[ni][1] = e1; acc[ni][2] = e2; acc[ni][3] = e3;
            slo += e0 + e1;  shi += e2 + e3;
        }
#pragma unroll
        for (int off = 1; off <= 2; off <<= 1) {
            slo += __shfl_xor_sync(0xffffffffu, slo, off);
            shi += __shfl_xor_sync(0xffffffffu, shi, off);
        }
        if (c == 0) {
            psum[(mr+g)  *2 + wn] = slo;
            psum[(mr+g+8)*2 + wn] = shi;
        }
        __syncthreads();
        const float tlo  = psum[(mr+g)*2]   + psum[(mr+g)*2+1];
        const float thi2 = psum[(mr+g+8)*2] + psum[(mr+g+8)*2+1];
        const float rlo = (tlo  > 0.f) ? (1.f / tlo)  : 0.f;
        const float rhi = (thi2 > 0.f) ? (1.f / thi2) : 0.f;

#pragma unroll
        for (int ni = 0; ni < 13; ni++) {
            const int col = nb + ni*8 + 2*c;
            uint2 ulo = make_uint2(f2tf32(acc[ni][0]*rlo), f2tf32(acc[ni][1]*rlo));
            uint2 uhi = make_uint2(f2tf32(acc[ni][2]*rhi), f2tf32(acc[ni][3]*rhi));
            *(uint2*)&Pt[(mr+g)  *PP + col] = ulo;
            *(uint2*)&Pt[(mr+g+8)*PP + col] = uhi;
        }
        __syncthreads();

        const int nb2 = wn * 40;
        float o[5][4];
#pragma unroll
        for (int ni = 0; ni < 5; ni++)
#pragma unroll
            for (int r = 0; r < 4; r++) o[ni][r] = 0.f;

        const int kcap   = (thi < T_-1) ? thi : (T_-1);
        const int ks_end = kcap >> 3;
        for (int ksb = 0; ksb <= ks_end; ksb++) {
            const int ks = ksb * 8;
            const uint32_t a0 = Pt[(mr+g)  *PP + ks+c];
            const uint32_t a1 = Pt[(mr+g+8)*PP + ks+c];
            const uint32_t a2 = Pt[(mr+g)  *PP + ks+c+4];
            const uint32_t a3 = Pt[(mr+g+8)*PP + ks+c+4];
#pragma unroll
            for (int ni = 0; ni < 5; ni++) {
                const uint32_t b0 = Vs[(ks+c)  *VP + nb2+ni*8+g];
                const uint32_t b1 = Vs[(ks+c+4)*VP + nb2+ni*8+g];
                mma_tf32(o[ni], a0, a1, a2, a3, b0, b1);
            }
        }

#pragma unroll
        for (int ni = 0; ni < 5; ni++) {
#pragma unroll
            for (int r = 0; r < 4; r++) {
                const int t = t0 + mr + g + ((r >= 2) ? 8 : 0);
                const int f = nb2 + ni*8 + 2*c + (r & 1);
                if (t < T_ && f < HS_)
                    g_att[((size_t)(b*T_ + t))*E_ + h*HS_ + f] = o[ni][r];
            }
        }
    }
}

// ---------------------------------------------------------------------------
extern "C" void kernel_launch(void* const* d_in, const int* in_sizes, int n_in,
                              void* d_out, int out_size)
{
    const float* x  = (const float*)d_in[0];
    const float* Wq = (const float*)d_in[1];
    const float* Wk = (const float*)d_in[2];
    const float* Wv = (const float*)d_in[3];
    const float* Wo = (const float*)d_in[4];
    const float* bo = (const float*)d_in[5];
    float* out = (float*)d_out;

    const int att_smem = (TP2*KQ2 + TP2*VP + 64*QP + 64*PP + 256) * (int)sizeof(float);
    cudaFuncSetAttribute(attn_mma, cudaFuncAttributeMaxDynamicSharedMemorySize, att_smem);

    // QKV projection: M=51200 -> 400 tiles of 128, N=1752 -> 14 tiles of 128
    gemm_tf32<0><<<dim3(14, 400), 256>>>(x, Wq, Wk, Wv, nullptr, nullptr);

    // attention (tensor-core)
    attn_mma<<<BH_, 256, att_smem>>>();

    // output projection: N=584 -> 5 tiles
    gemm_tf32<1><<<dim3(5, 400), 256>>>(nullptr, Wo, nullptr, nullptr, bo, out);
}